// round 14
// baseline (speedup 1.0000x reference)
#include <cuda_runtime.h>
#include <cuda_fp16.h>
#include <math.h>
#include <stdint.h>

#define NNODES 50000
#define MPAD   50048               // 391 * 128
#define DIM    256
#define NH     4
#define NEDGES 800000
#define EP     (NEDGES + NNODES)
#define NEG_SLOPE 0.2f
#define LN_EPS 1e-5f

#define SCAN_CHUNK 512
#define NCHUNK ((NNODES + SCAN_CHUNK - 1) / SCAN_CHUNK)

// ---------------- scratch ----------------
__device__ __half  g_hh[(size_t)NNODES * DIM];
__device__ float   g_r[(size_t)NNODES * DIM];
__device__ float   g_al_src[NNODES * NH];
__device__ float   g_al_dst[NNODES * NH];
__device__ __half  g_xh[(size_t)MPAD * DIM];
__device__ __half  g_wthi[512 * 256];  // [n][k] = Wcat[k][n], fp16 hi
__device__ __half  g_wtlo[512 * 256];  // residual lo
__device__ float   g_P[256 * 8];       // [d][j]: j<4 -> W·a_src head j, j>=4 -> W·a_dst
__device__ float   g_denom[NNODES * NH];   // softmax denominators
__device__ int     g_count[NNODES];
__device__ int     g_scan[NNODES];
__device__ int     g_bsum[NCHUNK];
__device__ int     g_boff[NCHUNK];
__device__ int     g_rowptr[NNODES + 1];
__device__ int     g_cursor[NNODES];
__device__ int     g_csr_src[EP];
__device__ float   g_csr_e[(size_t)EP * NH];   // exp(lrelu(logit))
__device__ int     g_is64;

__device__ __forceinline__ float lrelu(float x) { return x > 0.f ? x : NEG_SLOPE * x; }

__device__ __forceinline__ int edge_at(const void* ei, long long idx) {
    if (g_is64) return (int)((const long long*)ei)[idx];
    return ((const int*)ei)[idx];
}

// ---------------- detect + init counts ----------------
__global__ void detect_init_kernel(const int* __restrict__ ei_words) {
    int i = blockIdx.x * blockDim.x + threadIdx.x;
    if (i < NNODES) g_count[i] = 1;   // self loop
    if (i == 0) {
        int all0 = 1;
        for (int k = 0; k < 128; k++)
            if (ei_words[2 * k + 1] != 0) { all0 = 0; break; }
        g_is64 = all0;
    }
}

// ---------------- P = [W·a_src | W·a_dst], parallel ----------------
__global__ __launch_bounds__(256) void pmat_kernel(const float* __restrict__ W,
                                                   const float* __restrict__ a_src,
                                                   const float* __restrict__ a_dst) {
    int d = blockIdx.x;
    int t = threadIdx.x;
    int wid = t >> 5, lane = t & 31;
    float w = W[d * 256 + t];
    float ps = w * __ldg(&a_src[t]);
    float pd = w * __ldg(&a_dst[t]);
    #pragma unroll
    for (int o = 16; o > 0; o >>= 1) {
        ps += __shfl_xor_sync(0xffffffffu, ps, o);
        pd += __shfl_xor_sync(0xffffffffu, pd, o);
    }
    __shared__ float sps[8], spd[8];
    if (lane == 0) { sps[wid] = ps; spd[wid] = pd; }
    __syncthreads();
    if (t < 4) {
        g_P[d * 8 + t]     = sps[2 * t] + sps[2 * t + 1];
        g_P[d * 8 + 4 + t] = spd[2 * t] + spd[2 * t + 1];
    }
}

// ---------------- fused: x -> fp16 + exact fp32 logits ----------------
__global__ __launch_bounds__(256) void split_x_kernel(const float* __restrict__ x) {
    __shared__ float sP[256][9];
    int tid = threadIdx.x;
    for (int i = tid; i < 256 * 8; i += 256)
        sP[i >> 3][i & 7] = g_P[i];
    __syncthreads();

    int wid = tid >> 5, lane = tid & 31;
    long long n = (long long)blockIdx.x * 8 + wid;
    if (n >= MPAD) return;
    long long base = n * 256;
    int d0 = lane * 4, d1 = 128 + lane * 4;

    if (n >= NNODES) {
        __half z[4]; z[0] = z[1] = z[2] = z[3] = __float2half_rn(0.f);
        *reinterpret_cast<uint2*>(&g_xh[base + d0]) = *reinterpret_cast<uint2*>(z);
        *reinterpret_cast<uint2*>(&g_xh[base + d1]) = *reinterpret_cast<uint2*>(z);
        return;
    }

    float4 v0 = *reinterpret_cast<const float4*>(&x[base + d0]);
    float4 v1 = *reinterpret_cast<const float4*>(&x[base + d1]);
    __half h0[4], h1[4];
    h0[0] = __float2half_rn(v0.x); h0[1] = __float2half_rn(v0.y);
    h0[2] = __float2half_rn(v0.z); h0[3] = __float2half_rn(v0.w);
    h1[0] = __float2half_rn(v1.x); h1[1] = __float2half_rn(v1.y);
    h1[2] = __float2half_rn(v1.z); h1[3] = __float2half_rn(v1.w);
    *reinterpret_cast<uint2*>(&g_xh[base + d0]) = *reinterpret_cast<uint2*>(h0);
    *reinterpret_cast<uint2*>(&g_xh[base + d1]) = *reinterpret_cast<uint2*>(h1);

    float l[8] = {0.f, 0.f, 0.f, 0.f, 0.f, 0.f, 0.f, 0.f};
    float f0[4] = {v0.x, v0.y, v0.z, v0.w};
    float f1[4] = {v1.x, v1.y, v1.z, v1.w};
    #pragma unroll
    for (int i = 0; i < 4; i++) {
        #pragma unroll
        for (int j = 0; j < 8; j++) {
            l[j] = fmaf(f0[i], sP[d0 + i][j], l[j]);
            l[j] = fmaf(f1[i], sP[d1 + i][j], l[j]);
        }
    }
    #pragma unroll
    for (int j = 0; j < 8; j++) {
        #pragma unroll
        for (int o = 16; o > 0; o >>= 1)
            l[j] += __shfl_xor_sync(0xffffffffu, l[j], o);
    }
    if (lane < 4)      g_al_src[n * NH + lane] = l[lane];
    else if (lane < 8) g_al_dst[n * NH + (lane - 4)] = l[lane];
}

__global__ __launch_bounds__(256) void split_w_kernel(const float* __restrict__ W,
                                                      const float* __restrict__ Wres) {
    int idx = blockIdx.x * blockDim.x + threadIdx.x;
    if (idx >= 512 * 256) return;
    int n = idx >> 8, k = idx & 255;
    float v = (n < 256) ? W[k * 256 + n] : Wres[k * 256 + (n - 256)];
    __half hi = __float2half_rn(v);
    __half lo = __float2half_rn(v - __half2float(hi));
    g_wthi[idx] = hi;
    g_wtlo[idx] = lo;
}

// ---------------- 2-pass fp16 GEMM (split-B), 3-stage cp.async ----------
#define TILE_BYTES 10240              // 128 rows * 80B stride
#define STAGE_BYTES (3 * TILE_BYTES)  // A + Bhi + Blo
#define NSTAGE 3

__device__ __forceinline__ uint32_t smem_u32(const void* p) {
    uint32_t a;
    asm("{ .reg .u64 t; cvta.to.shared.u64 t, %1; cvt.u32.u64 %0, t; }" : "=r"(a) : "l"(p));
    return a;
}
__device__ __forceinline__ void cp16(uint32_t s, const void* g) {
    asm volatile("cp.async.cg.shared.global [%0], [%1], 16;" :: "r"(s), "l"(g));
}
#define CP_COMMIT() asm volatile("cp.async.commit_group;" ::: "memory")
#define CP_WAIT(n)  asm volatile("cp.async.wait_group %0;" :: "n"(n) : "memory")

__device__ __forceinline__ void ldsm4(uint32_t addr, uint32_t* d) {
    asm volatile("ldmatrix.sync.aligned.m8n8.x4.shared.b16 {%0,%1,%2,%3}, [%4];"
        : "=r"(d[0]), "=r"(d[1]), "=r"(d[2]), "=r"(d[3]) : "r"(addr));
}

__device__ __forceinline__ void mma_f16(float* c, const uint32_t* a, const uint32_t* b) {
    asm volatile(
        "mma.sync.aligned.m16n8k16.row.col.f32.f16.f16.f32 "
        "{%0,%1,%2,%3}, {%4,%5,%6,%7}, {%8,%9}, {%0,%1,%2,%3};\n"
        : "+f"(c[0]), "+f"(c[1]), "+f"(c[2]), "+f"(c[3])
        : "r"(a[0]), "r"(a[1]), "r"(a[2]), "r"(a[3]), "r"(b[0]), "r"(b[1]));
}

__global__ __launch_bounds__(256, 2) void f16_gemm_kernel()
{
    extern __shared__ char smem[];
    const uint32_t sbase = smem_u32(smem);
    const int tid = threadIdx.x;
    const int lane = tid & 31;
    const int warpId = tid >> 5;
    const int warpM = warpId & 3;
    const int warpN = warpId >> 2;
    const int blockRow = blockIdx.y * 128;
    const int cb = blockIdx.x;             // 0..3
    const bool isH = (cb < 2);
    const int bcol = cb * 128;

    const char* ah = reinterpret_cast<const char*>(g_xh) + (size_t)blockRow * 512;
    const char* whi = reinterpret_cast<const char*>(g_wthi) + (size_t)bcol * 512;
    const char* wlo = reinterpret_cast<const char*>(g_wtlo) + (size_t)bcol * 512;

    float acc[2][8][4];
    #pragma unroll
    for (int mt = 0; mt < 2; mt++)
        #pragma unroll
        for (int nt = 0; nt < 8; nt++)
            #pragma unroll
            for (int i = 0; i < 4; i++) acc[mt][nt][i] = 0.f;

    const int q = lane >> 3, r = lane & 7;
    const uint32_t aOff = (uint32_t)((warpM * 32 + (q & 1) * 8 + r) * 80 + (q >> 1) * 16);
    const uint32_t bOff = (uint32_t)((warpN * 64 + (q >> 1) * 8 + r) * 80 + (q & 1) * 16);

    auto load_stage = [&](int s, int c) {
        uint32_t stg = sbase + s * STAGE_BYTES;
        const int kb = c * 64;     // 32 fp16 = 64B per row chunk
        #pragma unroll
        for (int j = 0; j < 2; j++) {
            int idx = tid + j * 256;
            int row = idx >> 2, seg = idx & 3;
            uint32_t so = (uint32_t)(row * 80 + seg * 16);
            size_t go = (size_t)row * 512 + kb + seg * 16;
            cp16(stg + so,                  ah + go);
            cp16(stg + TILE_BYTES + so,     whi + go);
            cp16(stg + 2 * TILE_BYTES + so, wlo + go);
        }
    };

    load_stage(0, 0); CP_COMMIT();
    load_stage(1, 1); CP_COMMIT();

    for (int c = 0; c < 8; c++) {
        CP_WAIT(1);
        __syncthreads();

        const uint32_t stg = sbase + (uint32_t)(c % 3) * STAGE_BYTES;
        #pragma unroll
        for (int ks = 0; ks < 2; ks++) {
            const uint32_t kbyte = ks * 32;
            uint32_t Af[2][4];
            #pragma unroll
            for (int mt = 0; mt < 2; mt++)
                ldsm4(stg + aOff + mt * (16 * 80) + kbyte, Af[mt]);
            #pragma unroll
            for (int ntp = 0; ntp < 4; ntp++) {
                uint32_t Bh[4], Bl[4];
                ldsm4(stg + TILE_BYTES + bOff + ntp * (16 * 80) + kbyte, Bh);
                ldsm4(stg + 2 * TILE_BYTES + bOff + ntp * (16 * 80) + kbyte, Bl);
                #pragma unroll
                for (int mt = 0; mt < 2; mt++) {
                    mma_f16(acc[mt][ntp * 2],     Af[mt], Bh);
                    mma_f16(acc[mt][ntp * 2],     Af[mt], Bl);
                    mma_f16(acc[mt][ntp * 2 + 1], Af[mt], Bh + 2);
                    mma_f16(acc[mt][ntp * 2 + 1], Af[mt], Bl + 2);
                }
            }
        }

        if (c + 2 < 8) {
            load_stage((c + 2) % 3, c + 2);
            CP_COMMIT();
        }
    }

    // ---------------- epilogue ----------------
    #pragma unroll
    for (int mt = 0; mt < 2; mt++) {
        #pragma unroll
        for (int nt = 0; nt < 8; nt++) {
            int n_loc = warpN * 64 + nt * 8 + 2 * (lane & 3);
            int row0 = blockRow + warpM * 32 + mt * 16 + (lane >> 2);
            float c0 = acc[mt][nt][0], c1 = acc[mt][nt][1];
            float c2 = acc[mt][nt][2], c3 = acc[mt][nt][3];
            if (isH) {
                int gcol = bcol + n_loc;
                if (row0 < NNODES)
                    *reinterpret_cast<__half2*>(&g_hh[(size_t)row0 * DIM + gcol]) =
                        __floats2half2_rn(c0, c1);
                if (row0 + 8 < NNODES)
                    *reinterpret_cast<__half2*>(&g_hh[(size_t)(row0 + 8) * DIM + gcol]) =
                        __floats2half2_rn(c2, c3);
            } else {
                int gcol = (bcol - 256) + n_loc;
                if (row0 < NNODES)
                    *reinterpret_cast<float2*>(&g_r[(size_t)row0 * DIM + gcol]) =
                        make_float2(c0, c1);
                if (row0 + 8 < NNODES)
                    *reinterpret_cast<float2*>(&g_r[(size_t)(row0 + 8) * DIM + gcol]) =
                        make_float2(c2, c3);
            }
        }
    }
}

// ---------------- CSR build ----------------
__global__ void hist_kernel(const void* __restrict__ ei) {
    int i = blockIdx.x * blockDim.x + threadIdx.x;
    if (i < NEDGES) {
        int d = edge_at(ei, (long long)NEDGES + i);
        atomicAdd(&g_count[d], 1);
    }
}

__global__ __launch_bounds__(SCAN_CHUNK) void scan1_kernel() {
    __shared__ int s[SCAN_CHUNK];
    int i = blockIdx.x * SCAN_CHUNK + threadIdx.x;
    int v = (i < NNODES) ? g_count[i] : 0;
    s[threadIdx.x] = v;
    __syncthreads();
    for (int off = 1; off < SCAN_CHUNK; off <<= 1) {
        int t = s[threadIdx.x];
        int u = (threadIdx.x >= off) ? s[threadIdx.x - off] : 0;
        __syncthreads();
        s[threadIdx.x] = t + u;
        __syncthreads();
    }
    if (i < NNODES) g_scan[i] = s[threadIdx.x];
    if (threadIdx.x == SCAN_CHUNK - 1) g_bsum[blockIdx.x] = s[SCAN_CHUNK - 1];
}

__global__ void scan2_kernel() {
    if (threadIdx.x == 0 && blockIdx.x == 0) {
        int run = 0;
        for (int b = 0; b < NCHUNK; b++) { g_boff[b] = run; run += g_bsum[b]; }
    }
}

// self-loop entry + INITIALIZE denom with self exp (scatter adds the rest)
__global__ void scan3_kernel() {
    int i = blockIdx.x * blockDim.x + threadIdx.x;
    if (i >= NNODES) return;
    int cnt = g_count[i];
    int incl = g_scan[i] + g_boff[i / SCAN_CHUNK];
    int start = incl - cnt;
    g_rowptr[i] = start;
    g_cursor[i] = start + 1;
    g_csr_src[start] = i;
    float4 es = *reinterpret_cast<const float4*>(&g_al_src[i * NH]);
    float4 ed = *reinterpret_cast<const float4*>(&g_al_dst[i * NH]);
    float4 e = make_float4(expf(lrelu(es.x + ed.x)), expf(lrelu(es.y + ed.y)),
                           expf(lrelu(es.z + ed.z)), expf(lrelu(es.w + ed.w)));
    *reinterpret_cast<float4*>(&g_csr_e[(size_t)start * NH]) = e;
    *reinterpret_cast<float4*>(&g_denom[i * NH]) = e;
    if (i == NNODES - 1) g_rowptr[NNODES] = start + cnt;
}

__global__ void scatter_kernel(const void* __restrict__ ei) {
    int i = blockIdx.x * blockDim.x + threadIdx.x;
    if (i >= NEDGES) return;
    int s = edge_at(ei, i);
    int d = edge_at(ei, (long long)NEDGES + i);
    int pos = atomicAdd(&g_cursor[d], 1);
    g_csr_src[pos] = s;
    float4 es = *reinterpret_cast<const float4*>(&g_al_src[s * NH]);
    float4 ed = *reinterpret_cast<const float4*>(&g_al_dst[d * NH]);
    float4 e = make_float4(expf(lrelu(es.x + ed.x)), expf(lrelu(es.y + ed.y)),
                           expf(lrelu(es.z + ed.z)), expf(lrelu(es.w + ed.w)));
    *reinterpret_cast<float4*>(&g_csr_e[(size_t)pos * NH]) = e;
    atomicAdd(&g_denom[d * NH + 0], e.x);
    atomicAdd(&g_denom[d * NH + 1], e.y);
    atomicAdd(&g_denom[d * NH + 2], e.z);
    atomicAdd(&g_denom[d * NH + 3], e.w);
}

// ---------------- fused aggregate + residual + LayerNorm ----------
// No shared staging: CSR index/alpha loads are block-uniform -> warp broadcast.
__global__ __launch_bounds__(128) void aggregate_kernel(
    const float* __restrict__ bias_gat, const float* __restrict__ b_res,
    const float* __restrict__ gamma, const float* __restrict__ beta,
    float* __restrict__ out)
{
    int v = blockIdx.x;
    int tid = threadIdx.x;
    int start = g_rowptr[v];
    int deg = g_rowptr[v + 1] - start;
    const int hd = tid >> 5;

    __shared__ float s_s[4], s_q[4];

    const float inv = 1.f / (__ldg(&g_denom[v * NH + hd]) + 1e-16f);

    float2 acc = make_float2(0.f, 0.f);
    const __half2* hh2 = reinterpret_cast<const __half2*>(g_hh);
    const int* sv = g_csr_src + start;
    const float* ev = g_csr_e + (size_t)start * NH + hd;

    int j = 0;
    for (; j + 8 <= deg; j += 8) {
        int sidx[8]; float av[8];
        #pragma unroll
        for (int u = 0; u < 8; u++) {
            sidx[u] = __ldg(&sv[j + u]);
            av[u]   = __ldg(&ev[(j + u) * NH]) * inv;
        }
        float2 hv[8];
        #pragma unroll
        for (int u = 0; u < 8; u++)
            hv[u] = __half22float2(hh2[(size_t)sidx[u] * 128 + tid]);
        #pragma unroll
        for (int u = 0; u < 8; u++) {
            acc.x = fmaf(av[u], hv[u].x, acc.x);
            acc.y = fmaf(av[u], hv[u].y, acc.y);
        }
    }
    for (; j < deg; j++) {
        int s = __ldg(&sv[j]);
        float a = __ldg(&ev[j * NH]) * inv;
        float2 hv = __half22float2(hh2[(size_t)s * 128 + tid]);
        acc.x = fmaf(a, hv.x, acc.x);
        acc.y = fmaf(a, hv.y, acc.y);
    }

    float2 bg = *reinterpret_cast<const float2*>(&bias_gat[2 * tid]);
    float2 br = *reinterpret_cast<const float2*>(&b_res[2 * tid]);
    float2 rr = *reinterpret_cast<const float2*>(&g_r[(size_t)v * DIM + 2 * tid]);
    float y0 = acc.x + bg.x + rr.x + br.x;
    float y1 = acc.y + bg.y + rr.y + br.y;

    float sum = y0 + y1, sq = y0 * y0 + y1 * y1;
    #pragma unroll
    for (int o = 16; o > 0; o >>= 1) {
        sum += __shfl_xor_sync(0xffffffffu, sum, o);
        sq  += __shfl_xor_sync(0xffffffffu, sq, o);
    }
    int wid = tid >> 5, lane = tid & 31;
    if (lane == 0) { s_s[wid] = sum; s_q[wid] = sq; }
    __syncthreads();
    if (tid == 0) {
        float a = s_s[0] + s_s[1] + s_s[2] + s_s[3];
        float b = s_q[0] + s_q[1] + s_q[2] + s_q[3];
        float mu = a * (1.f / DIM);
        float var = b * (1.f / DIM) - mu * mu;
        s_s[0] = mu;
        s_q[0] = rsqrtf(var + LN_EPS);
    }
    __syncthreads();
    float mu = s_s[0], rstd = s_q[0];
    float2 gm = *reinterpret_cast<const float2*>(&gamma[2 * tid]);
    float2 bt = *reinterpret_cast<const float2*>(&beta[2 * tid]);
    float2 o2 = make_float2(gm.x * (y0 - mu) * rstd + bt.x,
                            gm.y * (y1 - mu) * rstd + bt.y);
    *reinterpret_cast<float2*>(&out[(size_t)v * DIM + 2 * tid]) = o2;
}

// ---------------- launch ----------------
extern "C" void kernel_launch(void* const* d_in, const int* in_sizes, int n_in,
                              void* d_out, int out_size)
{
    const float* x        = (const float*)d_in[0];
    const void*  ei       = d_in[1];
    const float* W        = (const float*)d_in[2];
    const float* a_src    = (const float*)d_in[3];
    const float* a_dst    = (const float*)d_in[4];
    const float* bias_gat = (const float*)d_in[5];
    const float* W_res    = (const float*)d_in[6];
    const float* b_res    = (const float*)d_in[7];
    const float* gamma    = (const float*)d_in[8];
    const float* beta     = (const float*)d_in[9];
    float* out = (float*)d_out;

    static int inited = 0;
    static cudaStream_t s2;
    static cudaEvent_t evDetect, evLogits, evCsr, evW;
    const int SMEM = NSTAGE * STAGE_BYTES;  // 92160
    if (!inited) {
        cudaFuncSetAttribute(f16_gemm_kernel, cudaFuncAttributeMaxDynamicSharedMemorySize, SMEM);
        cudaStreamCreateWithFlags(&s2, cudaStreamNonBlocking);
        cudaEventCreateWithFlags(&evDetect, cudaEventDisableTiming);
        cudaEventCreateWithFlags(&evLogits, cudaEventDisableTiming);
        cudaEventCreateWithFlags(&evCsr, cudaEventDisableTiming);
        cudaEventCreateWithFlags(&evW, cudaEventDisableTiming);
        inited = 1;
    }
    cudaStream_t s0 = (cudaStream_t)0;   // main (capture) stream

    // ---- main stream: prep ----
    detect_init_kernel<<<(NNODES + 255) / 256, 256, 0, s0>>>((const int*)ei);
    cudaEventRecord(evDetect, s0);
    pmat_kernel<<<256, 256, 0, s0>>>(W, a_src, a_dst);
    split_x_kernel<<<(MPAD + 7) / 8, 256, 0, s0>>>(x);     // fp16 convert + logits
    cudaEventRecord(evLogits, s0);

    // ---- side stream: forked from capture via evDetect wait (REQUIRED) ----
    cudaStreamWaitEvent(s2, evDetect, 0);
    split_w_kernel<<<(512 * 256 + 255) / 256, 256, 0, s2>>>(W, W_res);
    cudaEventRecord(evW, s2);
    hist_kernel<<<(NEDGES + 255) / 256, 256, 0, s2>>>(ei);
    scan1_kernel<<<NCHUNK, SCAN_CHUNK, 0, s2>>>();
    scan2_kernel<<<1, 32, 0, s2>>>();
    cudaStreamWaitEvent(s2, evLogits, 0);
    scan3_kernel<<<(NNODES + 255) / 256, 256, 0, s2>>>();
    scatter_kernel<<<(NEDGES + 255) / 256, 256, 0, s2>>>(ei);
    cudaEventRecord(evCsr, s2);

    // ---- main stream: GEMM (waits weight split; overlaps CSR chain) ----
    cudaStreamWaitEvent(s0, evW, 0);
    dim3 ggrid(4, MPAD / 128);
    f16_gemm_kernel<<<ggrid, 256, SMEM, s0>>>();

    // ---- join, then aggregate ----
    cudaStreamWaitEvent(s0, evCsr, 0);
    aggregate_kernel<<<NNODES, 128, 0, s0>>>(bias_gat, b_res, gamma, beta, out);
}

// round 16
// speedup vs baseline: 1.0305x; 1.0305x over previous
#include <cuda_runtime.h>
#include <cuda_fp16.h>
#include <math.h>
#include <stdint.h>

#define NNODES 50000
#define MPAD   50048               // 391 * 128
#define DIM    256
#define NH     4
#define NEDGES 800000
#define EP     (NEDGES + NNODES)
#define NEG_SLOPE 0.2f
#define LN_EPS 1e-5f

#define SCAN_CHUNK 512
#define NCHUNK ((NNODES + SCAN_CHUNK - 1) / SCAN_CHUNK)

// ---------------- scratch ----------------
__device__ __half  g_hh[(size_t)NNODES * DIM];
__device__ float   g_r[(size_t)NNODES * DIM];
__device__ float   g_al_src[NNODES * NH];
__device__ float   g_al_dst[NNODES * NH];
__device__ __half  g_xh[(size_t)MPAD * DIM];
__device__ __half  g_wthi[512 * 256];  // [n][k] = Wcat[k][n], fp16 hi
__device__ __half  g_wtlo[512 * 256];  // residual lo
__device__ float   g_P[256 * 8];       // [d][j]: j<4 -> W·a_src head j, j>=4 -> W·a_dst
__device__ float   g_denom[NNODES * NH];   // softmax denominators
__device__ int     g_count[NNODES];
__device__ int     g_scan[NNODES];
__device__ int     g_bsum[NCHUNK];
__device__ int     g_boff[NCHUNK];
__device__ int     g_rowptr[NNODES + 1];
__device__ int     g_cursor[NNODES];
__device__ int     g_csr_src[EP];
__device__ float   g_csr_e[(size_t)EP * NH];   // exp(lrelu(logit))
__device__ int     g_is64;

__device__ __forceinline__ float lrelu(float x) { return x > 0.f ? x : NEG_SLOPE * x; }

__device__ __forceinline__ int edge_at(const void* ei, long long idx) {
    if (g_is64) return (int)((const long long*)ei)[idx];
    return ((const int*)ei)[idx];
}

// ---------------- detect + init counts ----------------
__global__ void detect_init_kernel(const int* __restrict__ ei_words) {
    int i = blockIdx.x * blockDim.x + threadIdx.x;
    if (i < NNODES) g_count[i] = 1;   // self loop
    if (i == 0) {
        int all0 = 1;
        for (int k = 0; k < 128; k++)
            if (ei_words[2 * k + 1] != 0) { all0 = 0; break; }
        g_is64 = all0;
    }
}

// ---------------- P = [W·a_src | W·a_dst], parallel ----------------
__global__ __launch_bounds__(256) void pmat_kernel(const float* __restrict__ W,
                                                   const float* __restrict__ a_src,
                                                   const float* __restrict__ a_dst) {
    int d = blockIdx.x;
    int t = threadIdx.x;
    int wid = t >> 5, lane = t & 31;
    float w = W[d * 256 + t];
    float ps = w * __ldg(&a_src[t]);
    float pd = w * __ldg(&a_dst[t]);
    #pragma unroll
    for (int o = 16; o > 0; o >>= 1) {
        ps += __shfl_xor_sync(0xffffffffu, ps, o);
        pd += __shfl_xor_sync(0xffffffffu, pd, o);
    }
    __shared__ float sps[8], spd[8];
    if (lane == 0) { sps[wid] = ps; spd[wid] = pd; }
    __syncthreads();
    if (t < 4) {
        g_P[d * 8 + t]     = sps[2 * t] + sps[2 * t + 1];
        g_P[d * 8 + 4 + t] = spd[2 * t] + spd[2 * t + 1];
    }
}

// ---------------- fused: x -> fp16 + exact fp32 logits ----------------
__global__ __launch_bounds__(256) void split_x_kernel(const float* __restrict__ x) {
    __shared__ float sP[256][9];
    int tid = threadIdx.x;
    for (int i = tid; i < 256 * 8; i += 256)
        sP[i >> 3][i & 7] = g_P[i];
    __syncthreads();

    int wid = tid >> 5, lane = tid & 31;
    long long n = (long long)blockIdx.x * 8 + wid;
    if (n >= MPAD) return;
    long long base = n * 256;
    int d0 = lane * 4, d1 = 128 + lane * 4;

    if (n >= NNODES) {
        __half z[4]; z[0] = z[1] = z[2] = z[3] = __float2half_rn(0.f);
        *reinterpret_cast<uint2*>(&g_xh[base + d0]) = *reinterpret_cast<uint2*>(z);
        *reinterpret_cast<uint2*>(&g_xh[base + d1]) = *reinterpret_cast<uint2*>(z);
        return;
    }

    float4 v0 = *reinterpret_cast<const float4*>(&x[base + d0]);
    float4 v1 = *reinterpret_cast<const float4*>(&x[base + d1]);
    __half h0[4], h1[4];
    h0[0] = __float2half_rn(v0.x); h0[1] = __float2half_rn(v0.y);
    h0[2] = __float2half_rn(v0.z); h0[3] = __float2half_rn(v0.w);
    h1[0] = __float2half_rn(v1.x); h1[1] = __float2half_rn(v1.y);
    h1[2] = __float2half_rn(v1.z); h1[3] = __float2half_rn(v1.w);
    *reinterpret_cast<uint2*>(&g_xh[base + d0]) = *reinterpret_cast<uint2*>(h0);
    *reinterpret_cast<uint2*>(&g_xh[base + d1]) = *reinterpret_cast<uint2*>(h1);

    float l[8] = {0.f, 0.f, 0.f, 0.f, 0.f, 0.f, 0.f, 0.f};
    float f0[4] = {v0.x, v0.y, v0.z, v0.w};
    float f1[4] = {v1.x, v1.y, v1.z, v1.w};
    #pragma unroll
    for (int i = 0; i < 4; i++) {
        #pragma unroll
        for (int j = 0; j < 8; j++) {
            l[j] = fmaf(f0[i], sP[d0 + i][j], l[j]);
            l[j] = fmaf(f1[i], sP[d1 + i][j], l[j]);
        }
    }
    #pragma unroll
    for (int j = 0; j < 8; j++) {
        #pragma unroll
        for (int o = 16; o > 0; o >>= 1)
            l[j] += __shfl_xor_sync(0xffffffffu, l[j], o);
    }
    if (lane < 4)      g_al_src[n * NH + lane] = l[lane];
    else if (lane < 8) g_al_dst[n * NH + (lane - 4)] = l[lane];
}

__global__ __launch_bounds__(256) void split_w_kernel(const float* __restrict__ W,
                                                      const float* __restrict__ Wres) {
    int idx = blockIdx.x * blockDim.x + threadIdx.x;
    if (idx >= 512 * 256) return;
    int n = idx >> 8, k = idx & 255;
    float v = (n < 256) ? W[k * 256 + n] : Wres[k * 256 + (n - 256)];
    __half hi = __float2half_rn(v);
    __half lo = __float2half_rn(v - __half2float(hi));
    g_wthi[idx] = hi;
    g_wtlo[idx] = lo;
}

// ---------------- 2-pass fp16 GEMM (split-B), 3-stage cp.async ----------
#define TILE_BYTES 10240              // 128 rows * 80B stride
#define STAGE_BYTES (3 * TILE_BYTES)  // A + Bhi + Blo
#define NSTAGE 3

__device__ __forceinline__ uint32_t smem_u32(const void* p) {
    uint32_t a;
    asm("{ .reg .u64 t; cvta.to.shared.u64 t, %1; cvt.u32.u64 %0, t; }" : "=r"(a) : "l"(p));
    return a;
}
__device__ __forceinline__ void cp16(uint32_t s, const void* g) {
    asm volatile("cp.async.cg.shared.global [%0], [%1], 16;" :: "r"(s), "l"(g));
}
#define CP_COMMIT() asm volatile("cp.async.commit_group;" ::: "memory")
#define CP_WAIT(n)  asm volatile("cp.async.wait_group %0;" :: "n"(n) : "memory")

__device__ __forceinline__ void ldsm4(uint32_t addr, uint32_t* d) {
    asm volatile("ldmatrix.sync.aligned.m8n8.x4.shared.b16 {%0,%1,%2,%3}, [%4];"
        : "=r"(d[0]), "=r"(d[1]), "=r"(d[2]), "=r"(d[3]) : "r"(addr));
}

__device__ __forceinline__ void mma_f16(float* c, const uint32_t* a, const uint32_t* b) {
    asm volatile(
        "mma.sync.aligned.m16n8k16.row.col.f32.f16.f16.f32 "
        "{%0,%1,%2,%3}, {%4,%5,%6,%7}, {%8,%9}, {%0,%1,%2,%3};\n"
        : "+f"(c[0]), "+f"(c[1]), "+f"(c[2]), "+f"(c[3])
        : "r"(a[0]), "r"(a[1]), "r"(a[2]), "r"(a[3]), "r"(b[0]), "r"(b[1]));
}

__global__ __launch_bounds__(256, 2) void f16_gemm_kernel()
{
    extern __shared__ char smem[];
    const uint32_t sbase = smem_u32(smem);
    const int tid = threadIdx.x;
    const int lane = tid & 31;
    const int warpId = tid >> 5;
    const int warpM = warpId & 3;
    const int warpN = warpId >> 2;
    const int blockRow = blockIdx.y * 128;
    const int cb = blockIdx.x;             // 0..3
    const bool isH = (cb < 2);
    const int bcol = cb * 128;

    const char* ah = reinterpret_cast<const char*>(g_xh) + (size_t)blockRow * 512;
    const char* whi = reinterpret_cast<const char*>(g_wthi) + (size_t)bcol * 512;
    const char* wlo = reinterpret_cast<const char*>(g_wtlo) + (size_t)bcol * 512;

    float acc[2][8][4];
    #pragma unroll
    for (int mt = 0; mt < 2; mt++)
        #pragma unroll
        for (int nt = 0; nt < 8; nt++)
            #pragma unroll
            for (int i = 0; i < 4; i++) acc[mt][nt][i] = 0.f;

    const int q = lane >> 3, r = lane & 7;
    const uint32_t aOff = (uint32_t)((warpM * 32 + (q & 1) * 8 + r) * 80 + (q >> 1) * 16);
    const uint32_t bOff = (uint32_t)((warpN * 64 + (q >> 1) * 8 + r) * 80 + (q & 1) * 16);

    auto load_stage = [&](int s, int c) {
        uint32_t stg = sbase + s * STAGE_BYTES;
        const int kb = c * 64;     // 32 fp16 = 64B per row chunk
        #pragma unroll
        for (int j = 0; j < 2; j++) {
            int idx = tid + j * 256;
            int row = idx >> 2, seg = idx & 3;
            uint32_t so = (uint32_t)(row * 80 + seg * 16);
            size_t go = (size_t)row * 512 + kb + seg * 16;
            cp16(stg + so,                  ah + go);
            cp16(stg + TILE_BYTES + so,     whi + go);
            cp16(stg + 2 * TILE_BYTES + so, wlo + go);
        }
    };

    load_stage(0, 0); CP_COMMIT();
    load_stage(1, 1); CP_COMMIT();

    for (int c = 0; c < 8; c++) {
        CP_WAIT(1);
        __syncthreads();

        const uint32_t stg = sbase + (uint32_t)(c % 3) * STAGE_BYTES;
        #pragma unroll
        for (int ks = 0; ks < 2; ks++) {
            const uint32_t kbyte = ks * 32;
            uint32_t Af[2][4];
            #pragma unroll
            for (int mt = 0; mt < 2; mt++)
                ldsm4(stg + aOff + mt * (16 * 80) + kbyte, Af[mt]);
            #pragma unroll
            for (int ntp = 0; ntp < 4; ntp++) {
                uint32_t Bh[4], Bl[4];
                ldsm4(stg + TILE_BYTES + bOff + ntp * (16 * 80) + kbyte, Bh);
                ldsm4(stg + 2 * TILE_BYTES + bOff + ntp * (16 * 80) + kbyte, Bl);
                #pragma unroll
                for (int mt = 0; mt < 2; mt++) {
                    mma_f16(acc[mt][ntp * 2],     Af[mt], Bh);
                    mma_f16(acc[mt][ntp * 2],     Af[mt], Bl);
                    mma_f16(acc[mt][ntp * 2 + 1], Af[mt], Bh + 2);
                    mma_f16(acc[mt][ntp * 2 + 1], Af[mt], Bl + 2);
                }
            }
        }

        if (c + 2 < 8) {
            load_stage((c + 2) % 3, c + 2);
            CP_COMMIT();
        }
    }

    // ---------------- epilogue ----------------
    #pragma unroll
    for (int mt = 0; mt < 2; mt++) {
        #pragma unroll
        for (int nt = 0; nt < 8; nt++) {
            int n_loc = warpN * 64 + nt * 8 + 2 * (lane & 3);
            int row0 = blockRow + warpM * 32 + mt * 16 + (lane >> 2);
            float c0 = acc[mt][nt][0], c1 = acc[mt][nt][1];
            float c2 = acc[mt][nt][2], c3 = acc[mt][nt][3];
            if (isH) {
                int gcol = bcol + n_loc;
                if (row0 < NNODES)
                    *reinterpret_cast<__half2*>(&g_hh[(size_t)row0 * DIM + gcol]) =
                        __floats2half2_rn(c0, c1);
                if (row0 + 8 < NNODES)
                    *reinterpret_cast<__half2*>(&g_hh[(size_t)(row0 + 8) * DIM + gcol]) =
                        __floats2half2_rn(c2, c3);
            } else {
                int gcol = (bcol - 256) + n_loc;
                if (row0 < NNODES)
                    *reinterpret_cast<float2*>(&g_r[(size_t)row0 * DIM + gcol]) =
                        make_float2(c0, c1);
                if (row0 + 8 < NNODES)
                    *reinterpret_cast<float2*>(&g_r[(size_t)(row0 + 8) * DIM + gcol]) =
                        make_float2(c2, c3);
            }
        }
    }
}

// ---------------- CSR build ----------------
__global__ void hist_kernel(const void* __restrict__ ei) {
    int i = blockIdx.x * blockDim.x + threadIdx.x;
    if (i < NEDGES) {
        int d = edge_at(ei, (long long)NEDGES + i);
        atomicAdd(&g_count[d], 1);
    }
}

__global__ __launch_bounds__(SCAN_CHUNK) void scan1_kernel() {
    __shared__ int s[SCAN_CHUNK];
    int i = blockIdx.x * SCAN_CHUNK + threadIdx.x;
    int v = (i < NNODES) ? g_count[i] : 0;
    s[threadIdx.x] = v;
    __syncthreads();
    for (int off = 1; off < SCAN_CHUNK; off <<= 1) {
        int t = s[threadIdx.x];
        int u = (threadIdx.x >= off) ? s[threadIdx.x - off] : 0;
        __syncthreads();
        s[threadIdx.x] = t + u;
        __syncthreads();
    }
    if (i < NNODES) g_scan[i] = s[threadIdx.x];
    if (threadIdx.x == SCAN_CHUNK - 1) g_bsum[blockIdx.x] = s[SCAN_CHUNK - 1];
}

__global__ void scan2_kernel() {
    if (threadIdx.x == 0 && blockIdx.x == 0) {
        int run = 0;
        for (int b = 0; b < NCHUNK; b++) { g_boff[b] = run; run += g_bsum[b]; }
    }
}

// self-loop entry + INITIALIZE denom with self exp (scatter adds the rest)
__global__ void scan3_kernel() {
    int i = blockIdx.x * blockDim.x + threadIdx.x;
    if (i >= NNODES) return;
    int cnt = g_count[i];
    int incl = g_scan[i] + g_boff[i / SCAN_CHUNK];
    int start = incl - cnt;
    g_rowptr[i] = start;
    g_cursor[i] = start + 1;
    g_csr_src[start] = i;
    float4 es = *reinterpret_cast<const float4*>(&g_al_src[i * NH]);
    float4 ed = *reinterpret_cast<const float4*>(&g_al_dst[i * NH]);
    float4 e = make_float4(expf(lrelu(es.x + ed.x)), expf(lrelu(es.y + ed.y)),
                           expf(lrelu(es.z + ed.z)), expf(lrelu(es.w + ed.w)));
    *reinterpret_cast<float4*>(&g_csr_e[(size_t)start * NH]) = e;
    *reinterpret_cast<float4*>(&g_denom[i * NH]) = e;
    if (i == NNODES - 1) g_rowptr[NNODES] = start + cnt;
}

__global__ void scatter_kernel(const void* __restrict__ ei) {
    int i = blockIdx.x * blockDim.x + threadIdx.x;
    if (i >= NEDGES) return;
    int s = edge_at(ei, i);
    int d = edge_at(ei, (long long)NEDGES + i);
    int pos = atomicAdd(&g_cursor[d], 1);
    g_csr_src[pos] = s;
    float4 es = *reinterpret_cast<const float4*>(&g_al_src[s * NH]);
    float4 ed = *reinterpret_cast<const float4*>(&g_al_dst[d * NH]);
    float4 e = make_float4(expf(lrelu(es.x + ed.x)), expf(lrelu(es.y + ed.y)),
                           expf(lrelu(es.z + ed.z)), expf(lrelu(es.w + ed.w)));
    *reinterpret_cast<float4*>(&g_csr_e[(size_t)pos * NH]) = e;
    atomicAdd(&g_denom[d * NH + 0], e.x);
    atomicAdd(&g_denom[d * NH + 1], e.y);
    atomicAdd(&g_denom[d * NH + 2], e.z);
    atomicAdd(&g_denom[d * NH + 3], e.w);
}

// ---------------- fused aggregate + residual + LayerNorm ----------
// Shared staging (R13-proven) with double-buffered chunks: ONE barrier/chunk.
#define AGG_CH 128
__global__ __launch_bounds__(128) void aggregate_kernel(
    const float* __restrict__ bias_gat, const float* __restrict__ b_res,
    const float* __restrict__ gamma, const float* __restrict__ beta,
    float* __restrict__ out)
{
    int v = blockIdx.x;
    int tid = threadIdx.x;
    int start = g_rowptr[v];
    int deg = g_rowptr[v + 1] - start;

    __shared__ int   s_src[2][AGG_CH];
    __shared__ float s_alpha[2][AGG_CH * NH];
    __shared__ float s_s[4], s_q[4];

    float4 dn = *reinterpret_cast<const float4*>(&g_denom[v * NH]);
    const float inv0 = 1.f / (dn.x + 1e-16f);
    const float inv1 = 1.f / (dn.y + 1e-16f);
    const float inv2 = 1.f / (dn.z + 1e-16f);
    const float inv3 = 1.f / (dn.w + 1e-16f);

    const int hd = tid >> 5;
    float2 acc = make_float2(0.f, 0.f);
    const __half2* hh2 = reinterpret_cast<const __half2*>(g_hh);

    int buf = 0;
    for (int c0 = 0; c0 < deg; c0 += AGG_CH, buf ^= 1) {
        int len = min(AGG_CH, deg - c0);
        if (tid < len) {
            s_src[buf][tid] = g_csr_src[start + c0 + tid];
            float4 e = *reinterpret_cast<const float4*>(&g_csr_e[(size_t)(start + c0 + tid) * NH]);
            *reinterpret_cast<float4*>(&s_alpha[buf][tid * 4]) =
                make_float4(e.x * inv0, e.y * inv1, e.z * inv2, e.w * inv3);
        }
        __syncthreads();

        int j = 0;
        for (; j + 4 <= len; j += 4) {
            int sa = s_src[buf][j], sb = s_src[buf][j+1];
            int sc = s_src[buf][j+2], sd = s_src[buf][j+3];
            float a0 = s_alpha[buf][((j    ) << 2) | hd];
            float a1 = s_alpha[buf][((j + 1) << 2) | hd];
            float a2 = s_alpha[buf][((j + 2) << 2) | hd];
            float a3 = s_alpha[buf][((j + 3) << 2) | hd];
            float2 h0 = __half22float2(hh2[(size_t)sa * 128 + tid]);
            float2 h1 = __half22float2(hh2[(size_t)sb * 128 + tid]);
            float2 h2 = __half22float2(hh2[(size_t)sc * 128 + tid]);
            float2 h3 = __half22float2(hh2[(size_t)sd * 128 + tid]);
            acc.x = fmaf(a0, h0.x, acc.x); acc.y = fmaf(a0, h0.y, acc.y);
            acc.x = fmaf(a1, h1.x, acc.x); acc.y = fmaf(a1, h1.y, acc.y);
            acc.x = fmaf(a2, h2.x, acc.x); acc.y = fmaf(a2, h2.y, acc.y);
            acc.x = fmaf(a3, h3.x, acc.x); acc.y = fmaf(a3, h3.y, acc.y);
        }
        for (; j < len; j++) {
            float a = s_alpha[buf][(j << 2) | hd];
            float2 hv = __half22float2(hh2[(size_t)s_src[buf][j] * 128 + tid]);
            acc.x = fmaf(a, hv.x, acc.x);
            acc.y = fmaf(a, hv.y, acc.y);
        }
        // no trailing sync: next iteration writes the OTHER buffer; the
        // barrier inside iteration i+1 orders those writes against reads here.
    }

    float2 bg = *reinterpret_cast<const float2*>(&bias_gat[2 * tid]);
    float2 br = *reinterpret_cast<const float2*>(&b_res[2 * tid]);
    float2 rr = *reinterpret_cast<const float2*>(&g_r[(size_t)v * DIM + 2 * tid]);
    float y0 = acc.x + bg.x + rr.x + br.x;
    float y1 = acc.y + bg.y + rr.y + br.y;

    float sum = y0 + y1, sq = y0 * y0 + y1 * y1;
    #pragma unroll
    for (int o = 16; o > 0; o >>= 1) {
        sum += __shfl_xor_sync(0xffffffffu, sum, o);
        sq  += __shfl_xor_sync(0xffffffffu, sq, o);
    }
    int wid = tid >> 5, lane = tid & 31;
    if (lane == 0) { s_s[wid] = sum; s_q[wid] = sq; }
    __syncthreads();
    if (tid == 0) {
        float a = s_s[0] + s_s[1] + s_s[2] + s_s[3];
        float b = s_q[0] + s_q[1] + s_q[2] + s_q[3];
        float mu = a * (1.f / DIM);
        float var = b * (1.f / DIM) - mu * mu;
        s_s[0] = mu;
        s_q[0] = rsqrtf(var + LN_EPS);
    }
    __syncthreads();
    float mu = s_s[0], rstd = s_q[0];
    float2 gm = *reinterpret_cast<const float2*>(&gamma[2 * tid]);
    float2 bt = *reinterpret_cast<const float2*>(&beta[2 * tid]);
    float2 o2 = make_float2(gm.x * (y0 - mu) * rstd + bt.x,
                            gm.y * (y1 - mu) * rstd + bt.y);
    *reinterpret_cast<float2*>(&out[(size_t)v * DIM + 2 * tid]) = o2;
}

// ---------------- launch ----------------
extern "C" void kernel_launch(void* const* d_in, const int* in_sizes, int n_in,
                              void* d_out, int out_size)
{
    const float* x        = (const float*)d_in[0];
    const void*  ei       = d_in[1];
    const float* W        = (const float*)d_in[2];
    const float* a_src    = (const float*)d_in[3];
    const float* a_dst    = (const float*)d_in[4];
    const float* bias_gat = (const float*)d_in[5];
    const float* W_res    = (const float*)d_in[6];
    const float* b_res    = (const float*)d_in[7];
    const float* gamma    = (const float*)d_in[8];
    const float* beta     = (const float*)d_in[9];
    float* out = (float*)d_out;

    static int inited = 0;
    static cudaStream_t s2;
    static cudaEvent_t evDetect, evLogits, evCsr, evW;
    const int SMEM = NSTAGE * STAGE_BYTES;  // 92160
    if (!inited) {
        cudaFuncSetAttribute(f16_gemm_kernel, cudaFuncAttributeMaxDynamicSharedMemorySize, SMEM);
        cudaStreamCreateWithFlags(&s2, cudaStreamNonBlocking);
        cudaEventCreateWithFlags(&evDetect, cudaEventDisableTiming);
        cudaEventCreateWithFlags(&evLogits, cudaEventDisableTiming);
        cudaEventCreateWithFlags(&evCsr, cudaEventDisableTiming);
        cudaEventCreateWithFlags(&evW, cudaEventDisableTiming);
        inited = 1;
    }
    cudaStream_t s0 = (cudaStream_t)0;   // main (capture) stream

    // ---- main stream: prep ----
    detect_init_kernel<<<(NNODES + 255) / 256, 256, 0, s0>>>((const int*)ei);
    cudaEventRecord(evDetect, s0);
    pmat_kernel<<<256, 256, 0, s0>>>(W, a_src, a_dst);
    split_x_kernel<<<(MPAD + 7) / 8, 256, 0, s0>>>(x);     // fp16 convert + logits
    cudaEventRecord(evLogits, s0);

    // ---- side stream: forked from capture via evDetect wait (REQUIRED) ----
    cudaStreamWaitEvent(s2, evDetect, 0);
    split_w_kernel<<<(512 * 256 + 255) / 256, 256, 0, s2>>>(W, W_res);
    cudaEventRecord(evW, s2);
    hist_kernel<<<(NEDGES + 255) / 256, 256, 0, s2>>>(ei);
    scan1_kernel<<<NCHUNK, SCAN_CHUNK, 0, s2>>>();
    scan2_kernel<<<1, 32, 0, s2>>>();
    cudaStreamWaitEvent(s2, evLogits, 0);
    scan3_kernel<<<(NNODES + 255) / 256, 256, 0, s2>>>();
    scatter_kernel<<<(NEDGES + 255) / 256, 256, 0, s2>>>(ei);
    cudaEventRecord(evCsr, s2);

    // ---- main stream: GEMM (waits weight split; overlaps CSR chain) ----
    cudaStreamWaitEvent(s0, evW, 0);
    dim3 ggrid(4, MPAD / 128);
    f16_gemm_kernel<<<ggrid, 256, SMEM, s0>>>();

    // ---- join, then aggregate ----
    cudaStreamWaitEvent(s0, evCsr, 0);
    aggregate_kernel<<<NNODES, 128, 0, s0>>>(bias_gat, b_res, gamma, beta, out);
}

// round 17
// speedup vs baseline: 1.2018x; 1.1663x over previous
#include <cuda_runtime.h>
#include <cuda_fp16.h>
#include <math.h>
#include <stdint.h>

#define NNODES 50000
#define MPAD   50048               // 391 * 128
#define DIM    256
#define NH     4
#define NEDGES 800000
#define EP     (NEDGES + NNODES)
#define NEG_SLOPE 0.2f
#define LN_EPS 1e-5f

#define SCAN_CHUNK 512
#define NCHUNK ((NNODES + SCAN_CHUNK - 1) / SCAN_CHUNK)

// ---------------- scratch ----------------
__device__ __half  g_hh[(size_t)NNODES * DIM];
__device__ float   g_r[(size_t)NNODES * DIM];
__device__ float   g_al_src[NNODES * NH];
__device__ float   g_al_dst[NNODES * NH];
__device__ __half  g_xh[(size_t)MPAD * DIM];
__device__ __half  g_wthi[512 * 256];  // [n][k] = Wcat[k][n], fp16 hi
__device__ __half  g_wtlo[512 * 256];  // residual lo
__device__ float   g_P[256 * 8];       // [d][j]: j<4 -> W·a_src head j, j>=4 -> W·a_dst
__device__ float   g_denom[NNODES * NH];   // softmax denominators
__device__ int     g_count[NNODES];
__device__ int     g_scan[NNODES];
__device__ int     g_bsum[NCHUNK];
__device__ int     g_boff[NCHUNK];
__device__ int     g_rowptr[NNODES + 1];
__device__ int     g_cursor[NNODES];
__device__ int     g_csr_src[EP];
__device__ float   g_csr_e[(size_t)EP * NH];   // exp(lrelu(logit))
__device__ int     g_is64;

__device__ __forceinline__ float lrelu(float x) { return x > 0.f ? x : NEG_SLOPE * x; }

__device__ __forceinline__ int edge_at(const void* ei, long long idx) {
    if (g_is64) return (int)((const long long*)ei)[idx];
    return ((const int*)ei)[idx];
}

// ---------------- detect + init counts ----------------
__global__ void detect_init_kernel(const int* __restrict__ ei_words) {
    int i = blockIdx.x * blockDim.x + threadIdx.x;
    if (i < NNODES) g_count[i] = 1;   // self loop
    if (i == 0) {
        int all0 = 1;
        for (int k = 0; k < 128; k++)
            if (ei_words[2 * k + 1] != 0) { all0 = 0; break; }
        g_is64 = all0;
    }
}

// ---------------- P = [W·a_src | W·a_dst], parallel ----------------
__global__ __launch_bounds__(256) void pmat_kernel(const float* __restrict__ W,
                                                   const float* __restrict__ a_src,
                                                   const float* __restrict__ a_dst) {
    int d = blockIdx.x;
    int t = threadIdx.x;
    int wid = t >> 5, lane = t & 31;
    float w = W[d * 256 + t];
    float ps = w * __ldg(&a_src[t]);
    float pd = w * __ldg(&a_dst[t]);
    #pragma unroll
    for (int o = 16; o > 0; o >>= 1) {
        ps += __shfl_xor_sync(0xffffffffu, ps, o);
        pd += __shfl_xor_sync(0xffffffffu, pd, o);
    }
    __shared__ float sps[8], spd[8];
    if (lane == 0) { sps[wid] = ps; spd[wid] = pd; }
    __syncthreads();
    if (t < 4) {
        g_P[d * 8 + t]     = sps[2 * t] + sps[2 * t + 1];
        g_P[d * 8 + 4 + t] = spd[2 * t] + spd[2 * t + 1];
    }
}

// ---------------- fused: x -> fp16 + exact fp32 logits ----------------
__global__ __launch_bounds__(256) void split_x_kernel(const float* __restrict__ x) {
    __shared__ float sP[256][9];
    int tid = threadIdx.x;
    for (int i = tid; i < 256 * 8; i += 256)
        sP[i >> 3][i & 7] = g_P[i];
    __syncthreads();

    int wid = tid >> 5, lane = tid & 31;
    long long n = (long long)blockIdx.x * 8 + wid;
    if (n >= MPAD) return;
    long long base = n * 256;
    int d0 = lane * 4, d1 = 128 + lane * 4;

    if (n >= NNODES) {
        __half z[4]; z[0] = z[1] = z[2] = z[3] = __float2half_rn(0.f);
        *reinterpret_cast<uint2*>(&g_xh[base + d0]) = *reinterpret_cast<uint2*>(z);
        *reinterpret_cast<uint2*>(&g_xh[base + d1]) = *reinterpret_cast<uint2*>(z);
        return;
    }

    float4 v0 = *reinterpret_cast<const float4*>(&x[base + d0]);
    float4 v1 = *reinterpret_cast<const float4*>(&x[base + d1]);
    __half h0[4], h1[4];
    h0[0] = __float2half_rn(v0.x); h0[1] = __float2half_rn(v0.y);
    h0[2] = __float2half_rn(v0.z); h0[3] = __float2half_rn(v0.w);
    h1[0] = __float2half_rn(v1.x); h1[1] = __float2half_rn(v1.y);
    h1[2] = __float2half_rn(v1.z); h1[3] = __float2half_rn(v1.w);
    *reinterpret_cast<uint2*>(&g_xh[base + d0]) = *reinterpret_cast<uint2*>(h0);
    *reinterpret_cast<uint2*>(&g_xh[base + d1]) = *reinterpret_cast<uint2*>(h1);

    float l[8] = {0.f, 0.f, 0.f, 0.f, 0.f, 0.f, 0.f, 0.f};
    float f0[4] = {v0.x, v0.y, v0.z, v0.w};
    float f1[4] = {v1.x, v1.y, v1.z, v1.w};
    #pragma unroll
    for (int i = 0; i < 4; i++) {
        #pragma unroll
        for (int j = 0; j < 8; j++) {
            l[j] = fmaf(f0[i], sP[d0 + i][j], l[j]);
            l[j] = fmaf(f1[i], sP[d1 + i][j], l[j]);
        }
    }
    #pragma unroll
    for (int j = 0; j < 8; j++) {
        #pragma unroll
        for (int o = 16; o > 0; o >>= 1)
            l[j] += __shfl_xor_sync(0xffffffffu, l[j], o);
    }
    if (lane < 4)      g_al_src[n * NH + lane] = l[lane];
    else if (lane < 8) g_al_dst[n * NH + (lane - 4)] = l[lane];
}

__global__ __launch_bounds__(256) void split_w_kernel(const float* __restrict__ W,
                                                      const float* __restrict__ Wres) {
    int idx = blockIdx.x * blockDim.x + threadIdx.x;
    if (idx >= 512 * 256) return;
    int n = idx >> 8, k = idx & 255;
    float v = (n < 256) ? W[k * 256 + n] : Wres[k * 256 + (n - 256)];
    __half hi = __float2half_rn(v);
    __half lo = __float2half_rn(v - __half2float(hi));
    g_wthi[idx] = hi;
    g_wtlo[idx] = lo;
}

// ---------------- 2-pass fp16 GEMM (split-B), 3-stage cp.async ----------
#define TILE_BYTES 10240              // 128 rows * 80B stride
#define STAGE_BYTES (3 * TILE_BYTES)  // A + Bhi + Blo
#define NSTAGE 3

__device__ __forceinline__ uint32_t smem_u32(const void* p) {
    uint32_t a;
    asm("{ .reg .u64 t; cvta.to.shared.u64 t, %1; cvt.u32.u64 %0, t; }" : "=r"(a) : "l"(p));
    return a;
}
__device__ __forceinline__ void cp16(uint32_t s, const void* g) {
    asm volatile("cp.async.cg.shared.global [%0], [%1], 16;" :: "r"(s), "l"(g));
}
#define CP_COMMIT() asm volatile("cp.async.commit_group;" ::: "memory")
#define CP_WAIT(n)  asm volatile("cp.async.wait_group %0;" :: "n"(n) : "memory")

__device__ __forceinline__ void ldsm4(uint32_t addr, uint32_t* d) {
    asm volatile("ldmatrix.sync.aligned.m8n8.x4.shared.b16 {%0,%1,%2,%3}, [%4];"
        : "=r"(d[0]), "=r"(d[1]), "=r"(d[2]), "=r"(d[3]) : "r"(addr));
}

__device__ __forceinline__ void mma_f16(float* c, const uint32_t* a, const uint32_t* b) {
    asm volatile(
        "mma.sync.aligned.m16n8k16.row.col.f32.f16.f16.f32 "
        "{%0,%1,%2,%3}, {%4,%5,%6,%7}, {%8,%9}, {%0,%1,%2,%3};\n"
        : "+f"(c[0]), "+f"(c[1]), "+f"(c[2]), "+f"(c[3])
        : "r"(a[0]), "r"(a[1]), "r"(a[2]), "r"(a[3]), "r"(b[0]), "r"(b[1]));
}

__global__ __launch_bounds__(256, 2) void f16_gemm_kernel()
{
    extern __shared__ char smem[];
    const uint32_t sbase = smem_u32(smem);
    const int tid = threadIdx.x;
    const int lane = tid & 31;
    const int warpId = tid >> 5;
    const int warpM = warpId & 3;
    const int warpN = warpId >> 2;
    const int blockRow = blockIdx.y * 128;
    const int cb = blockIdx.x;             // 0..3
    const bool isH = (cb < 2);
    const int bcol = cb * 128;

    const char* ah = reinterpret_cast<const char*>(g_xh) + (size_t)blockRow * 512;
    const char* whi = reinterpret_cast<const char*>(g_wthi) + (size_t)bcol * 512;
    const char* wlo = reinterpret_cast<const char*>(g_wtlo) + (size_t)bcol * 512;

    float acc[2][8][4];
    #pragma unroll
    for (int mt = 0; mt < 2; mt++)
        #pragma unroll
        for (int nt = 0; nt < 8; nt++)
            #pragma unroll
            for (int i = 0; i < 4; i++) acc[mt][nt][i] = 0.f;

    const int q = lane >> 3, r = lane & 7;
    const uint32_t aOff = (uint32_t)((warpM * 32 + (q & 1) * 8 + r) * 80 + (q >> 1) * 16);
    const uint32_t bOff = (uint32_t)((warpN * 64 + (q >> 1) * 8 + r) * 80 + (q & 1) * 16);

    auto load_stage = [&](int s, int c) {
        uint32_t stg = sbase + s * STAGE_BYTES;
        const int kb = c * 64;     // 32 fp16 = 64B per row chunk
        #pragma unroll
        for (int j = 0; j < 2; j++) {
            int idx = tid + j * 256;
            int row = idx >> 2, seg = idx & 3;
            uint32_t so = (uint32_t)(row * 80 + seg * 16);
            size_t go = (size_t)row * 512 + kb + seg * 16;
            cp16(stg + so,                  ah + go);
            cp16(stg + TILE_BYTES + so,     whi + go);
            cp16(stg + 2 * TILE_BYTES + so, wlo + go);
        }
    };

    load_stage(0, 0); CP_COMMIT();
    load_stage(1, 1); CP_COMMIT();

    for (int c = 0; c < 8; c++) {
        CP_WAIT(1);
        __syncthreads();

        const uint32_t stg = sbase + (uint32_t)(c % 3) * STAGE_BYTES;
        #pragma unroll
        for (int ks = 0; ks < 2; ks++) {
            const uint32_t kbyte = ks * 32;
            uint32_t Af[2][4];
            #pragma unroll
            for (int mt = 0; mt < 2; mt++)
                ldsm4(stg + aOff + mt * (16 * 80) + kbyte, Af[mt]);
            #pragma unroll
            for (int ntp = 0; ntp < 4; ntp++) {
                uint32_t Bh[4], Bl[4];
                ldsm4(stg + TILE_BYTES + bOff + ntp * (16 * 80) + kbyte, Bh);
                ldsm4(stg + 2 * TILE_BYTES + bOff + ntp * (16 * 80) + kbyte, Bl);
                #pragma unroll
                for (int mt = 0; mt < 2; mt++) {
                    mma_f16(acc[mt][ntp * 2],     Af[mt], Bh);
                    mma_f16(acc[mt][ntp * 2],     Af[mt], Bl);
                    mma_f16(acc[mt][ntp * 2 + 1], Af[mt], Bh + 2);
                    mma_f16(acc[mt][ntp * 2 + 1], Af[mt], Bl + 2);
                }
            }
        }

        if (c + 2 < 8) {
            load_stage((c + 2) % 3, c + 2);
            CP_COMMIT();
        }
    }

    // ---------------- epilogue ----------------
    #pragma unroll
    for (int mt = 0; mt < 2; mt++) {
        #pragma unroll
        for (int nt = 0; nt < 8; nt++) {
            int n_loc = warpN * 64 + nt * 8 + 2 * (lane & 3);
            int row0 = blockRow + warpM * 32 + mt * 16 + (lane >> 2);
            float c0 = acc[mt][nt][0], c1 = acc[mt][nt][1];
            float c2 = acc[mt][nt][2], c3 = acc[mt][nt][3];
            if (isH) {
                int gcol = bcol + n_loc;
                if (row0 < NNODES)
                    *reinterpret_cast<__half2*>(&g_hh[(size_t)row0 * DIM + gcol]) =
                        __floats2half2_rn(c0, c1);
                if (row0 + 8 < NNODES)
                    *reinterpret_cast<__half2*>(&g_hh[(size_t)(row0 + 8) * DIM + gcol]) =
                        __floats2half2_rn(c2, c3);
            } else {
                int gcol = (bcol - 256) + n_loc;
                if (row0 < NNODES)
                    *reinterpret_cast<float2*>(&g_r[(size_t)row0 * DIM + gcol]) =
                        make_float2(c0, c1);
                if (row0 + 8 < NNODES)
                    *reinterpret_cast<float2*>(&g_r[(size_t)(row0 + 8) * DIM + gcol]) =
                        make_float2(c2, c3);
            }
        }
    }
}

// ---------------- CSR build ----------------
__global__ void hist_kernel(const void* __restrict__ ei) {
    int i = blockIdx.x * blockDim.x + threadIdx.x;
    if (i < NEDGES) {
        int d = edge_at(ei, (long long)NEDGES + i);
        atomicAdd(&g_count[d], 1);
    }
}

__global__ __launch_bounds__(SCAN_CHUNK) void scan1_kernel() {
    __shared__ int s[SCAN_CHUNK];
    int i = blockIdx.x * SCAN_CHUNK + threadIdx.x;
    int v = (i < NNODES) ? g_count[i] : 0;
    s[threadIdx.x] = v;
    __syncthreads();
    for (int off = 1; off < SCAN_CHUNK; off <<= 1) {
        int t = s[threadIdx.x];
        int u = (threadIdx.x >= off) ? s[threadIdx.x - off] : 0;
        __syncthreads();
        s[threadIdx.x] = t + u;
        __syncthreads();
    }
    if (i < NNODES) g_scan[i] = s[threadIdx.x];
    if (threadIdx.x == SCAN_CHUNK - 1) g_bsum[blockIdx.x] = s[SCAN_CHUNK - 1];
}

__global__ void scan2_kernel() {
    if (threadIdx.x == 0 && blockIdx.x == 0) {
        int run = 0;
        for (int b = 0; b < NCHUNK; b++) { g_boff[b] = run; run += g_bsum[b]; }
    }
}

// self-loop entry + INITIALIZE denom with self exp (scatter adds the rest)
__global__ void scan3_kernel() {
    int i = blockIdx.x * blockDim.x + threadIdx.x;
    if (i >= NNODES) return;
    int cnt = g_count[i];
    int incl = g_scan[i] + g_boff[i / SCAN_CHUNK];
    int start = incl - cnt;
    g_rowptr[i] = start;
    g_cursor[i] = start + 1;
    g_csr_src[start] = i;
    float4 es = *reinterpret_cast<const float4*>(&g_al_src[i * NH]);
    float4 ed = *reinterpret_cast<const float4*>(&g_al_dst[i * NH]);
    float4 e = make_float4(expf(lrelu(es.x + ed.x)), expf(lrelu(es.y + ed.y)),
                           expf(lrelu(es.z + ed.z)), expf(lrelu(es.w + ed.w)));
    *reinterpret_cast<float4*>(&g_csr_e[(size_t)start * NH]) = e;
    *reinterpret_cast<float4*>(&g_denom[i * NH]) = e;
    if (i == NNODES - 1) g_rowptr[NNODES] = start + cnt;
}

__global__ void scatter_kernel(const void* __restrict__ ei) {
    int i = blockIdx.x * blockDim.x + threadIdx.x;
    if (i >= NEDGES) return;
    int s = edge_at(ei, i);
    int d = edge_at(ei, (long long)NEDGES + i);
    int pos = atomicAdd(&g_cursor[d], 1);
    g_csr_src[pos] = s;
    float4 es = *reinterpret_cast<const float4*>(&g_al_src[s * NH]);
    float4 ed = *reinterpret_cast<const float4*>(&g_al_dst[d * NH]);
    float4 e = make_float4(expf(lrelu(es.x + ed.x)), expf(lrelu(es.y + ed.y)),
                           expf(lrelu(es.z + ed.z)), expf(lrelu(es.w + ed.w)));
    *reinterpret_cast<float4*>(&g_csr_e[(size_t)pos * NH]) = e;
    atomicAdd(&g_denom[d * NH + 0], e.x);
    atomicAdd(&g_denom[d * NH + 1], e.y);
    atomicAdd(&g_denom[d * NH + 2], e.z);
    atomicAdd(&g_denom[d * NH + 3], e.w);
}

// ---------------- fused aggregate + residual + LayerNorm ----------
// WARP PER NODE: lane owns 8 channels (16B). One LDG.128 per gathered row.
// LayerNorm fully warp-local: no shared memory, no block barriers.
__global__ __launch_bounds__(128) void aggregate_kernel(
    const float* __restrict__ bias_gat, const float* __restrict__ b_res,
    const float* __restrict__ gamma, const float* __restrict__ beta,
    float* __restrict__ out)
{
    int v = (blockIdx.x * blockDim.x + threadIdx.x) >> 5;
    int lane = threadIdx.x & 31;
    if (v >= NNODES) return;

    int start = g_rowptr[v];
    int deg = g_rowptr[v + 1] - start;
    const int hd = lane >> 3;   // channels lane*8..+7 belong to head (lane*8)/64

    const float inv = 1.f / (__ldg(&g_denom[v * NH + hd]) + 1e-16f);

    float acc[8];
    #pragma unroll
    for (int k = 0; k < 8; k++) acc[k] = 0.f;

    const uint4* hh4 = reinterpret_cast<const uint4*>(g_hh);  // 16B units; 32/row
    const int* sv = g_csr_src + start;
    const float* ev = g_csr_e + (size_t)start * NH + hd;

    int j = 0;
    for (; j + 4 <= deg; j += 4) {
        int s0 = __ldg(&sv[j]),     s1 = __ldg(&sv[j + 1]);
        int s2 = __ldg(&sv[j + 2]), s3 = __ldg(&sv[j + 3]);
        float a0 = __ldg(&ev[(j    ) * NH]) * inv;
        float a1 = __ldg(&ev[(j + 1) * NH]) * inv;
        float a2 = __ldg(&ev[(j + 2) * NH]) * inv;
        float a3 = __ldg(&ev[(j + 3) * NH]) * inv;
        uint4 p0 = __ldg(&hh4[(size_t)s0 * 32 + lane]);
        uint4 p1 = __ldg(&hh4[(size_t)s1 * 32 + lane]);
        uint4 p2 = __ldg(&hh4[(size_t)s2 * 32 + lane]);
        uint4 p3 = __ldg(&hh4[(size_t)s3 * 32 + lane]);
        const uint32_t* w0 = &p0.x; const uint32_t* w1 = &p1.x;
        const uint32_t* w2 = &p2.x; const uint32_t* w3 = &p3.x;
        #pragma unroll
        for (int q = 0; q < 4; q++) {
            float2 f0 = __half22float2(*reinterpret_cast<const __half2*>(&w0[q]));
            float2 f1 = __half22float2(*reinterpret_cast<const __half2*>(&w1[q]));
            float2 f2 = __half22float2(*reinterpret_cast<const __half2*>(&w2[q]));
            float2 f3 = __half22float2(*reinterpret_cast<const __half2*>(&w3[q]));
            acc[2*q]   = fmaf(a0, f0.x, acc[2*q]);   acc[2*q+1] = fmaf(a0, f0.y, acc[2*q+1]);
            acc[2*q]   = fmaf(a1, f1.x, acc[2*q]);   acc[2*q+1] = fmaf(a1, f1.y, acc[2*q+1]);
            acc[2*q]   = fmaf(a2, f2.x, acc[2*q]);   acc[2*q+1] = fmaf(a2, f2.y, acc[2*q+1]);
            acc[2*q]   = fmaf(a3, f3.x, acc[2*q]);   acc[2*q+1] = fmaf(a3, f3.y, acc[2*q+1]);
        }
    }
    for (; j < deg; j++) {
        int s = __ldg(&sv[j]);
        float a = __ldg(&ev[j * NH]) * inv;
        uint4 p = __ldg(&hh4[(size_t)s * 32 + lane]);
        const uint32_t* w = &p.x;
        #pragma unroll
        for (int q = 0; q < 4; q++) {
            float2 f = __half22float2(*reinterpret_cast<const __half2*>(&w[q]));
            acc[2*q]   = fmaf(a, f.x, acc[2*q]);
            acc[2*q+1] = fmaf(a, f.y, acc[2*q+1]);
        }
    }

    // ---- bias + residual (channels c = lane*8 .. lane*8+7) ----
    int c0 = lane * 8;
    float4 bg0 = *reinterpret_cast<const float4*>(&bias_gat[c0]);
    float4 bg1 = *reinterpret_cast<const float4*>(&bias_gat[c0 + 4]);
    float4 br0 = *reinterpret_cast<const float4*>(&b_res[c0]);
    float4 br1 = *reinterpret_cast<const float4*>(&b_res[c0 + 4]);
    float4 rr0 = *reinterpret_cast<const float4*>(&g_r[(size_t)v * DIM + c0]);
    float4 rr1 = *reinterpret_cast<const float4*>(&g_r[(size_t)v * DIM + c0 + 4]);
    float y[8];
    y[0] = acc[0] + bg0.x + rr0.x + br0.x;
    y[1] = acc[1] + bg0.y + rr0.y + br0.y;
    y[2] = acc[2] + bg0.z + rr0.z + br0.z;
    y[3] = acc[3] + bg0.w + rr0.w + br0.w;
    y[4] = acc[4] + bg1.x + rr1.x + br1.x;
    y[5] = acc[5] + bg1.y + rr1.y + br1.y;
    y[6] = acc[6] + bg1.z + rr1.z + br1.z;
    y[7] = acc[7] + bg1.w + rr1.w + br1.w;

    // ---- warp-local LayerNorm over 256 channels ----
    float sum = 0.f, sq = 0.f;
    #pragma unroll
    for (int k = 0; k < 8; k++) { sum += y[k]; sq += y[k] * y[k]; }
    #pragma unroll
    for (int o = 16; o > 0; o >>= 1) {
        sum += __shfl_xor_sync(0xffffffffu, sum, o);
        sq  += __shfl_xor_sync(0xffffffffu, sq, o);
    }
    float mu = sum * (1.f / DIM);
    float var = sq * (1.f / DIM) - mu * mu;
    float rstd = rsqrtf(var + LN_EPS);

    float4 gm0 = *reinterpret_cast<const float4*>(&gamma[c0]);
    float4 gm1 = *reinterpret_cast<const float4*>(&gamma[c0 + 4]);
    float4 bt0 = *reinterpret_cast<const float4*>(&beta[c0]);
    float4 bt1 = *reinterpret_cast<const float4*>(&beta[c0 + 4]);
    float4 o0, o1;
    o0.x = gm0.x * (y[0] - mu) * rstd + bt0.x;
    o0.y = gm0.y * (y[1] - mu) * rstd + bt0.y;
    o0.z = gm0.z * (y[2] - mu) * rstd + bt0.z;
    o0.w = gm0.w * (y[3] - mu) * rstd + bt0.w;
    o1.x = gm1.x * (y[4] - mu) * rstd + bt1.x;
    o1.y = gm1.y * (y[5] - mu) * rstd + bt1.y;
    o1.z = gm1.z * (y[6] - mu) * rstd + bt1.z;
    o1.w = gm1.w * (y[7] - mu) * rstd + bt1.w;
    *reinterpret_cast<float4*>(&out[(size_t)v * DIM + c0])     = o0;
    *reinterpret_cast<float4*>(&out[(size_t)v * DIM + c0 + 4]) = o1;
}

// ---------------- launch ----------------
extern "C" void kernel_launch(void* const* d_in, const int* in_sizes, int n_in,
                              void* d_out, int out_size)
{
    const float* x        = (const float*)d_in[0];
    const void*  ei       = d_in[1];
    const float* W        = (const float*)d_in[2];
    const float* a_src    = (const float*)d_in[3];
    const float* a_dst    = (const float*)d_in[4];
    const float* bias_gat = (const float*)d_in[5];
    const float* W_res    = (const float*)d_in[6];
    const float* b_res    = (const float*)d_in[7];
    const float* gamma    = (const float*)d_in[8];
    const float* beta     = (const float*)d_in[9];
    float* out = (float*)d_out;

    static int inited = 0;
    static cudaStream_t s2;
    static cudaEvent_t evDetect, evLogits, evCsr, evW;
    const int SMEM = NSTAGE * STAGE_BYTES;  // 92160
    if (!inited) {
        cudaFuncSetAttribute(f16_gemm_kernel, cudaFuncAttributeMaxDynamicSharedMemorySize, SMEM);
        cudaStreamCreateWithFlags(&s2, cudaStreamNonBlocking);
        cudaEventCreateWithFlags(&evDetect, cudaEventDisableTiming);
        cudaEventCreateWithFlags(&evLogits, cudaEventDisableTiming);
        cudaEventCreateWithFlags(&evCsr, cudaEventDisableTiming);
        cudaEventCreateWithFlags(&evW, cudaEventDisableTiming);
        inited = 1;
    }
    cudaStream_t s0 = (cudaStream_t)0;   // main (capture) stream

    // ---- main stream: prep ----
    detect_init_kernel<<<(NNODES + 255) / 256, 256, 0, s0>>>((const int*)ei);
    cudaEventRecord(evDetect, s0);
    pmat_kernel<<<256, 256, 0, s0>>>(W, a_src, a_dst);
    split_x_kernel<<<(MPAD + 7) / 8, 256, 0, s0>>>(x);     // fp16 convert + logits
    cudaEventRecord(evLogits, s0);

    // ---- side stream: forked from capture via evDetect wait (REQUIRED) ----
    cudaStreamWaitEvent(s2, evDetect, 0);
    split_w_kernel<<<(512 * 256 + 255) / 256, 256, 0, s2>>>(W, W_res);
    cudaEventRecord(evW, s2);
    hist_kernel<<<(NEDGES + 255) / 256, 256, 0, s2>>>(ei);
    scan1_kernel<<<NCHUNK, SCAN_CHUNK, 0, s2>>>();
    scan2_kernel<<<1, 32, 0, s2>>>();
    cudaStreamWaitEvent(s2, evLogits, 0);
    scan3_kernel<<<(NNODES + 255) / 256, 256, 0, s2>>>();
    scatter_kernel<<<(NEDGES + 255) / 256, 256, 0, s2>>>(ei);
    cudaEventRecord(evCsr, s2);

    // ---- main stream: GEMM (waits weight split; overlaps CSR chain) ----
    cudaStreamWaitEvent(s0, evW, 0);
    dim3 ggrid(4, MPAD / 128);
    f16_gemm_kernel<<<ggrid, 256, SMEM, s0>>>();

    // ---- join, then aggregate (warp per node: 4 nodes / 128-thread block) ----
    cudaStreamWaitEvent(s0, evCsr, 0);
    aggregate_kernel<<<(NNODES * 32 + 127) / 128, 128, 0, s0>>>(bias_gat, b_res, gamma, beta, out);
}